// round 7
// baseline (speedup 1.0000x reference)
#include <cuda_runtime.h>
#include <cuda_fp16.h>
#include <cstdint>

#define NN 200000
#define NF 400000
#define NE (3*NF)

#define NBLK 196          // scan blocks (196*1024 >= NN)
#define KH 256            // h1 width
#define BM 128
#define BN 256
#define BK 32

// -------- scratch (zero-initialized at module load; every replay restores) ----
__device__ int g_deg[NN];            // reset by k_layer1
__device__ float g_s1[3 * NN];       // reset by k_layer1
__device__ int g_flag[NBLK];         // reset by k_fill
__device__ float g_gsum[128];        // reset by k_final
__device__ int g_rowptr[NN + 1];
__device__ int g_cursor[NN];
__device__ int g_aggval[NBLK];
__device__ int g_incval[NBLK];
__device__ int g_colidx[NE];
__device__ __half g_h1[(size_t)NN * 256];   // 102.4 MB
__device__ __half g_t[(size_t)NN * 128];    // 51.2 MB (gathered)
__device__ __half g_u[(size_t)NN * 128];    // 51.2 MB (streamed)
__device__ __half g_Wc[256 * 256];          // [k][n]: fp16(W2l|W2r)

// ---------------- helpers -----------------------------------------------------
__device__ __forceinline__ void edge_decode(const int* __restrict__ face, int e,
                                            int& src, int& dst) {
    int t = e / NF;
    int f = e - t * NF;
    if (t == 0)      { src = face[f];          dst = face[NF + f];     }
    else if (t == 1) { src = face[NF + f];     dst = face[2 * NF + f]; }
    else             { src = face[f];          dst = face[2 * NF + f]; }
}

// ---- L1: hist + edge-parallel pos aggregation + fp16 weight conversion -------
__global__ void k_hist(const int* __restrict__ face, const float* __restrict__ pos,
                       const float* __restrict__ W2l, const float* __restrict__ W2r) {
    int i = blockIdx.x * blockDim.x + threadIdx.x;
    if (i < 256 * 256) {
        int k = i >> 8, c = i & 255;
        float w = (c < 128) ? W2l[k * 128 + c] : W2r[k * 128 + (c - 128)];
        g_Wc[k * 256 + c] = __float2half_rn(w);
    }
    if (i >= NE) return;
    int src, dst;
    edge_decode(face, i, src, dst);
    if (src != dst) {
        atomicAdd(&g_deg[dst], 1);
        atomicAdd(&g_s1[3 * dst + 0], pos[3 * src + 0]);
        atomicAdd(&g_s1[3 * dst + 1], pos[3 * src + 1]);
        atomicAdd(&g_s1[3 * dst + 2], pos[3 * src + 2]);
    }
}

// ---- L2: single-pass decoupled-lookback scan (rowptr + cursor) ---------------
__global__ void k_scan() {
    __shared__ int s[1024];
    __shared__ int sprefix;
    int b = blockIdx.x;
    int tid = threadIdx.x;
    int i = b * 1024 + tid;
    int v = (i < NN) ? g_deg[i] : 0;
    s[tid] = v;
    __syncthreads();
    #pragma unroll
    for (int off = 1; off < 1024; off <<= 1) {
        int t = (tid >= off) ? s[tid - off] : 0;
        __syncthreads();
        s[tid] += t;
        __syncthreads();
    }
    int total = s[1023];
    if (tid == 0) {
        if (b == 0) {
            g_incval[0] = total;
            __threadfence();
            atomicExch(&g_flag[0], 2);
            sprefix = 0;
        } else {
            g_aggval[b] = total;
            __threadfence();
            atomicExch(&g_flag[b], 1);
            int prefix = 0;
            int j = b - 1;
            while (j >= 0) {
                int f;
                do { f = atomicAdd(&g_flag[j], 0); } while (f == 0);
                if (f == 2) { prefix += g_incval[j]; break; }
                prefix += g_aggval[j];
                j--;
            }
            g_incval[b] = prefix + total;
            __threadfence();
            atomicExch(&g_flag[b], 2);
            sprefix = prefix;
        }
    }
    __syncthreads();
    int p = sprefix;
    if (i < NN) {
        int r = p + s[tid] - v;   // exclusive
        g_rowptr[i] = r;
        g_cursor[i] = r;
    }
    if (b == NBLK - 1 && tid == 1023) g_rowptr[NN] = p + total;
}

// ---- L3: layer-1 dense (reads s1/deg, restores them to 0) -> h1 fp16 ---------
__global__ void k_layer1(const float* __restrict__ pos, const float* __restrict__ W1l,
                         const float* __restrict__ W1r, const float* __restrict__ b1) {
    __shared__ float sw[1792];
    for (int i = threadIdx.x; i < 1792; i += blockDim.x)
        sw[i] = (i < 768) ? W1l[i] : (i < 1536 ? W1r[i - 768] : b1[i - 1536]);
    __syncthreads();
    const float* wl = sw;
    const float* wr = sw + 768;
    const float* bb = sw + 1536;

    int wid = threadIdx.x >> 5, lane = threadIdx.x & 31;
    int node = blockIdx.x * (blockDim.x >> 5) + wid;
    if (node >= NN) return;

    int deg = g_deg[node];
    float inv = 1.0f / fmaxf((float)deg, 1.0f);
    float ax = g_s1[3 * node + 0] * inv;
    float ay = g_s1[3 * node + 1] * inv;
    float az = g_s1[3 * node + 2] * inv;
    // restore invariant for next replay
    if (lane == 0) {
        g_deg[node] = 0;
        g_s1[3 * node + 0] = 0.0f;
        g_s1[3 * node + 1] = 0.0f;
        g_s1[3 * node + 2] = 0.0f;
    }

    float px = pos[3 * node + 0], py = pos[3 * node + 1], pz = pos[3 * node + 2];

    int c0 = lane * 8;
    uint4 outv;
    unsigned* po = (unsigned*)&outv;
    #pragma unroll
    for (int t = 0; t < 4; t++) {
        int c = c0 + 2 * t;
        float h0 = bb[c] + ax * wl[c] + ay * wl[256 + c] + az * wl[512 + c]
                         + px * wr[c] + py * wr[256 + c] + pz * wr[512 + c];
        int c1 = c + 1;
        float h1v = bb[c1] + ax * wl[c1] + ay * wl[256 + c1] + az * wl[512 + c1]
                           + px * wr[c1] + py * wr[256 + c1] + pz * wr[512 + c1];
        h0 = fmaxf(h0, 0.0f);
        h1v = fmaxf(h1v, 0.0f);
        __half2 p2 = __floats2half2_rn(h0, h1v);
        po[t] = *(unsigned*)&p2;
    }
    ((uint4*)(g_h1 + (size_t)node * 256))[lane] = outv;
}

// ---- L4 (PROFILED SLOT): fp16 mma GEMM  [t|u] = h1 @ Wc -----------------------
__global__ void __launch_bounds__(512, 1) k_gemm() {
    __shared__ __half As[BM][BK + 24];   // stride 112B (conflict-free ldmatrix)
    __shared__ __half Bs[BK][BN + 8];    // stride 528B

    int tid = threadIdx.x;
    int warp = tid >> 5, lane = tid & 31;
    int wm = warp & 3, wn = warp >> 2;   // 4(M) x 4(N) warps; warp tile 32x64
    int bm = blockIdx.x * BM;

    float c[2][8][4];
    #pragma unroll
    for (int mi = 0; mi < 2; mi++)
        #pragma unroll
        for (int ni = 0; ni < 8; ni++)
            #pragma unroll
            for (int q = 0; q < 4; q++) c[mi][ni][q] = 0.0f;

    for (int k0 = 0; k0 < KH; k0 += BK) {
        {
            int row = tid >> 2, cq = tid & 3;
            int node = bm + row;
            uint4 val = make_uint4(0, 0, 0, 0);
            if (node < NN) val = *(const uint4*)(g_h1 + (size_t)node * 256 + k0 + cq * 8);
            *(uint4*)(&As[row][cq * 8]) = val;
        }
        #pragma unroll
        for (int r = 0; r < 2; r++) {
            int u = tid + 512 * r;
            int row = u >> 5, cq = u & 31;
            *(uint4*)(&Bs[row][cq * 8]) =
                *(const uint4*)(g_Wc + (size_t)(k0 + row) * 256 + cq * 8);
        }
        __syncthreads();

        #pragma unroll
        for (int kk = 0; kk < BK; kk += 16) {
            uint32_t a[2][4];
            #pragma unroll
            for (int mi = 0; mi < 2; mi++) {
                int r = wm * 32 + mi * 16 + (lane & 7) + 8 * ((lane >> 3) & 1);
                int cc = kk + 8 * (lane >> 4);
                uint32_t addr = (uint32_t)__cvta_generic_to_shared(&As[r][cc]);
                asm volatile("ldmatrix.sync.aligned.m8n8.x4.shared.b16 {%0,%1,%2,%3}, [%4];"
                             : "=r"(a[mi][0]), "=r"(a[mi][1]), "=r"(a[mi][2]), "=r"(a[mi][3])
                             : "r"(addr));
            }
            int rr = kk + (lane & 7) + 8 * ((lane >> 3) & 1);
            #pragma unroll
            for (int np = 0; np < 4; np++) {
                int ncol = wn * 64 + np * 16 + 8 * (lane >> 4);
                uint32_t b[4];
                uint32_t baddr = (uint32_t)__cvta_generic_to_shared(&Bs[rr][ncol]);
                asm volatile("ldmatrix.sync.aligned.m8n8.x4.trans.shared.b16 {%0,%1,%2,%3}, [%4];"
                             : "=r"(b[0]), "=r"(b[1]), "=r"(b[2]), "=r"(b[3])
                             : "r"(baddr));
                #pragma unroll
                for (int mi = 0; mi < 2; mi++) {
                    #pragma unroll
                    for (int h = 0; h < 2; h++) {
                        int ni = np * 2 + h;
                        asm volatile(
                            "mma.sync.aligned.m16n8k16.row.col.f32.f16.f16.f32 "
                            "{%0,%1,%2,%3},{%4,%5,%6,%7},{%8,%9},{%0,%1,%2,%3};"
                            : "+f"(c[mi][ni][0]), "+f"(c[mi][ni][1]),
                              "+f"(c[mi][ni][2]), "+f"(c[mi][ni][3])
                            : "r"(a[mi][0]), "r"(a[mi][1]), "r"(a[mi][2]), "r"(a[mi][3]),
                              "r"(b[2 * h]), "r"(b[2 * h + 1]));
                    }
                }
            }
        }
        __syncthreads();
    }

    int gid = lane >> 2, qid = lane & 3;
    #pragma unroll
    for (int mi = 0; mi < 2; mi++) {
        int r0 = bm + wm * 32 + mi * 16 + gid;
        int r1 = r0 + 8;
        #pragma unroll
        for (int ni = 0; ni < 8; ni++) {
            int col = wn * 64 + ni * 8 + qid * 2;
            __half* base0;
            int cc;
            if (col < 128) { base0 = g_t; cc = col; }
            else           { base0 = g_u; cc = col - 128; }
            if (r0 < NN) {
                __half2 p = __floats2half2_rn(c[mi][ni][0], c[mi][ni][1]);
                *(unsigned*)(base0 + (size_t)r0 * 128 + cc) = *(unsigned*)&p;
            }
            if (r1 < NN) {
                __half2 p = __floats2half2_rn(c[mi][ni][2], c[mi][ni][3]);
                *(unsigned*)(base0 + (size_t)r1 * 128 + cc) = *(unsigned*)&p;
            }
        }
    }
}

// ---- L5: fill CSR (+ restore scan flags) --------------------------------------
__global__ void k_fill(const int* __restrict__ face) {
    int e = blockIdx.x * blockDim.x + threadIdx.x;
    if (e < NBLK) g_flag[e] = 0;            // restore invariant (scan already done)
    if (e >= NE) return;
    int src, dst;
    edge_decode(face, e, src, dst);
    if (src != dst) {
        int p = atomicAdd(&g_cursor[dst], 1);
        g_colidx[p] = src;
    }
}

// ---- L6: layer-2 aggregate + relu + mean-pool ---------------------------------
__global__ void k_layer2(const float* __restrict__ b2) {
    __shared__ float gsh[128];
    if (threadIdx.x < 128) gsh[threadIdx.x] = 0.0f;
    __syncthreads();

    int wid = threadIdx.x >> 5, lane = threadIdx.x & 31;
    int gwarp = blockIdx.x * (blockDim.x >> 5) + wid;
    int nwarps = gridDim.x * (blockDim.x >> 5);
    float4 bl = ((const float4*)b2)[lane];

    float a0 = 0.f, a1 = 0.f, a2 = 0.f, a3 = 0.f;
    for (int node = gwarp; node < NN; node += nwarps) {
        int beg = g_rowptr[node], end = g_rowptr[node + 1];
        float s0 = 0.f, s1 = 0.f, s2 = 0.f, s3 = 0.f;
        #pragma unroll 4
        for (int j = beg; j < end; j++) {
            int src = g_colidx[j];
            uint2 tv = ((const uint2*)(g_t + (size_t)src * 128))[lane];
            float2 t01 = __half22float2(*(__half2*)&tv.x);
            float2 t23 = __half22float2(*(__half2*)&tv.y);
            s0 += t01.x; s1 += t01.y;
            s2 += t23.x; s3 += t23.y;
        }
        float inv = 1.0f / fmaxf((float)(end - beg), 1.0f);
        uint2 uv = ((const uint2*)(g_u + (size_t)node * 128))[lane];
        float2 u01 = __half22float2(*(__half2*)&uv.x);
        float2 u23 = __half22float2(*(__half2*)&uv.y);
        a0 += fmaxf(s0 * inv + u01.x + bl.x, 0.0f);
        a1 += fmaxf(s1 * inv + u01.y + bl.y, 0.0f);
        a2 += fmaxf(s2 * inv + u23.x + bl.z, 0.0f);
        a3 += fmaxf(s3 * inv + u23.y + bl.w, 0.0f);
    }
    atomicAdd(&gsh[lane * 4 + 0], a0);
    atomicAdd(&gsh[lane * 4 + 1], a1);
    atomicAdd(&gsh[lane * 4 + 2], a2);
    atomicAdd(&gsh[lane * 4 + 3], a3);
    __syncthreads();
    if (threadIdx.x < 128) atomicAdd(&g_gsum[threadIdx.x], gsh[threadIdx.x]);
}

// ---- L7: decoder + softmax + argmax (+ restore gsum) ---------------------------
__global__ void k_final(const float* __restrict__ Wd, const float* __restrict__ bd,
                        float* __restrict__ out, int out_size) {
    if (threadIdx.x != 0 || blockIdx.x != 0) return;
    float g[128];
    for (int c = 0; c < 128; c++) {
        g[c] = g_gsum[c] * (1.0f / (float)NN);
        g_gsum[c] = 0.0f;   // restore invariant
    }
    float lg[10];
    for (int j = 0; j < 10; j++) lg[j] = bd[j];
    for (int c = 0; c < 128; c++) {
        float gv = g[c];
        for (int j = 0; j < 10; j++) lg[j] += gv * Wd[c * 10 + j];
    }
    float m = lg[0];
    for (int j = 1; j < 10; j++) m = fmaxf(m, lg[j]);
    float e[10], s = 0.0f;
    for (int j = 0; j < 10; j++) { e[j] = expf(lg[j] - m); s += e[j]; }
    float invs = 1.0f / s;
    int am = 0;
    float best = -1.0f;
    for (int j = 0; j < 10; j++) {
        float p = e[j] * invs;
        if (j < out_size) out[j] = p;
        if (p > best) { best = p; am = j; }
    }
    for (int i = 10; i < out_size; i++) out[i] = (float)am;
}

// ---------------- launch --------------------------------------------------------
extern "C" void kernel_launch(void* const* d_in, const int* in_sizes, int n_in,
                              void* d_out, int out_size) {
    const float* pos = (const float*)d_in[0];
    const int*   face = (const int*)d_in[1];
    const float* W1l = (const float*)d_in[2];
    const float* W1r = (const float*)d_in[3];
    const float* b1  = (const float*)d_in[4];
    const float* W2l = (const float*)d_in[5];
    const float* W2r = (const float*)d_in[6];
    const float* b2  = (const float*)d_in[7];
    const float* Wd  = (const float*)d_in[8];
    const float* bd  = (const float*)d_in[9];
    float* out = (float*)d_out;

    k_hist   <<<(NE + 255) / 256, 256>>>(face, pos, W2l, W2r);  // 1
    k_scan   <<<NBLK, 1024>>>();                                // 2
    k_layer1 <<<(NN + 7) / 8, 256>>>(pos, W1l, W1r, b1);        // 3
    k_gemm   <<<(NN + BM - 1) / BM, 512>>>();                   // 4  <- profiled
    k_fill   <<<(NE + 255) / 256, 256>>>(face);                 // 5
    k_layer2 <<<1184, 256>>>(b2);                               // 6
    k_final  <<<1, 32>>>(Wd, bd, out, out_size);                // 7
}

// round 8
// speedup vs baseline: 1.0714x; 1.0714x over previous
#include <cuda_runtime.h>
#include <cuda_fp16.h>
#include <cstdint>

#define NN 200000
#define NF 400000
#define NE (3*NF)

#define NBLK 196          // scan blocks (196*1024 >= NN)
#define KH 256            // h1 width
#define BM 64
#define BN 256
#define BK 32

// -------- scratch (zero-initialized at module load; every replay restores) ----
__device__ int g_deg[NN];            // reset by k_layer1
__device__ float g_s1[3 * NN];       // reset by k_layer1
__device__ int g_flag[NBLK];         // reset by k_fill
__device__ float g_gsum[128];        // reset by k_final
__device__ int g_rowptr[NN + 1];
__device__ int g_cursor[NN];
__device__ int g_aggval[NBLK];
__device__ int g_incval[NBLK];
__device__ int g_colidx[NE];
__device__ __half g_h1[(size_t)NN * 256];   // 102.4 MB
__device__ __half g_t[(size_t)NN * 128];    // 51.2 MB (gathered)
__device__ __half g_u[(size_t)NN * 128];    // 51.2 MB (streamed)
__device__ __half g_Wc[256 * 256];          // [k][n]: fp16(W2l|W2r)

// ---- L1: face-parallel hist + pos aggregation + fp16 weight conversion -------
__global__ void k_hist(const int* __restrict__ face, const float* __restrict__ pos,
                       const float* __restrict__ W2l, const float* __restrict__ W2r) {
    int i = blockIdx.x * blockDim.x + threadIdx.x;
    if (i < 256 * 256) {
        int k = i >> 8, c = i & 255;
        float w = (c < 128) ? W2l[k * 128 + c] : W2r[k * 128 + (c - 128)];
        g_Wc[k * 256 + c] = __float2half_rn(w);
    }
    if (i >= NF) return;
    int v0 = face[i], v1 = face[NF + i], v2 = face[2 * NF + i];
    float p0x = pos[3 * v0 + 0], p0y = pos[3 * v0 + 1], p0z = pos[3 * v0 + 2];
    if (v0 != v1) {   // edge v0 -> v1
        atomicAdd(&g_deg[v1], 1);
        atomicAdd(&g_s1[3 * v1 + 0], p0x);
        atomicAdd(&g_s1[3 * v1 + 1], p0y);
        atomicAdd(&g_s1[3 * v1 + 2], p0z);
    }
    if (v1 != v2) {   // edge v1 -> v2
        atomicAdd(&g_deg[v2], 1);
        atomicAdd(&g_s1[3 * v2 + 0], pos[3 * v1 + 0]);
        atomicAdd(&g_s1[3 * v2 + 1], pos[3 * v1 + 1]);
        atomicAdd(&g_s1[3 * v2 + 2], pos[3 * v1 + 2]);
    }
    if (v0 != v2) {   // edge v0 -> v2
        atomicAdd(&g_deg[v2], 1);
        atomicAdd(&g_s1[3 * v2 + 0], p0x);
        atomicAdd(&g_s1[3 * v2 + 1], p0y);
        atomicAdd(&g_s1[3 * v2 + 2], p0z);
    }
}

// ---- L2: single-pass decoupled-lookback scan (rowptr + cursor) ---------------
__global__ void k_scan() {
    __shared__ int s[1024];
    __shared__ int sprefix;
    int b = blockIdx.x;
    int tid = threadIdx.x;
    int i = b * 1024 + tid;
    int v = (i < NN) ? g_deg[i] : 0;
    s[tid] = v;
    __syncthreads();
    #pragma unroll
    for (int off = 1; off < 1024; off <<= 1) {
        int t = (tid >= off) ? s[tid - off] : 0;
        __syncthreads();
        s[tid] += t;
        __syncthreads();
    }
    int total = s[1023];
    if (tid == 0) {
        if (b == 0) {
            g_incval[0] = total;
            __threadfence();
            atomicExch(&g_flag[0], 2);
            sprefix = 0;
        } else {
            g_aggval[b] = total;
            __threadfence();
            atomicExch(&g_flag[b], 1);
            int prefix = 0;
            int j = b - 1;
            while (j >= 0) {
                int f;
                do { f = atomicAdd(&g_flag[j], 0); } while (f == 0);
                if (f == 2) { prefix += g_incval[j]; break; }
                prefix += g_aggval[j];
                j--;
            }
            g_incval[b] = prefix + total;
            __threadfence();
            atomicExch(&g_flag[b], 2);
            sprefix = prefix;
        }
    }
    __syncthreads();
    int p = sprefix;
    if (i < NN) {
        int r = p + s[tid] - v;   // exclusive
        g_rowptr[i] = r;
        g_cursor[i] = r;
    }
    if (b == NBLK - 1 && tid == 1023) g_rowptr[NN] = p + total;
}

// ---- L3: layer-1 dense (reads s1/deg, restores them to 0) -> h1 fp16 ---------
__global__ void k_layer1(const float* __restrict__ pos, const float* __restrict__ W1l,
                         const float* __restrict__ W1r, const float* __restrict__ b1) {
    __shared__ float sw[1792];
    for (int i = threadIdx.x; i < 1792; i += blockDim.x)
        sw[i] = (i < 768) ? W1l[i] : (i < 1536 ? W1r[i - 768] : b1[i - 1536]);
    __syncthreads();
    const float* wl = sw;
    const float* wr = sw + 768;
    const float* bb = sw + 1536;

    int wid = threadIdx.x >> 5, lane = threadIdx.x & 31;
    int node = blockIdx.x * (blockDim.x >> 5) + wid;
    if (node >= NN) return;

    int deg = g_deg[node];
    float inv = 1.0f / fmaxf((float)deg, 1.0f);
    float ax = g_s1[3 * node + 0] * inv;
    float ay = g_s1[3 * node + 1] * inv;
    float az = g_s1[3 * node + 2] * inv;
    if (lane == 0) {   // restore invariant for next replay
        g_deg[node] = 0;
        g_s1[3 * node + 0] = 0.0f;
        g_s1[3 * node + 1] = 0.0f;
        g_s1[3 * node + 2] = 0.0f;
    }

    float px = pos[3 * node + 0], py = pos[3 * node + 1], pz = pos[3 * node + 2];

    int c0 = lane * 8;
    uint4 outv;
    unsigned* po = (unsigned*)&outv;
    #pragma unroll
    for (int t = 0; t < 4; t++) {
        int c = c0 + 2 * t;
        float h0 = bb[c] + ax * wl[c] + ay * wl[256 + c] + az * wl[512 + c]
                         + px * wr[c] + py * wr[256 + c] + pz * wr[512 + c];
        int c1 = c + 1;
        float h1v = bb[c1] + ax * wl[c1] + ay * wl[256 + c1] + az * wl[512 + c1]
                           + px * wr[c1] + py * wr[256 + c1] + pz * wr[512 + c1];
        h0 = fmaxf(h0, 0.0f);
        h1v = fmaxf(h1v, 0.0f);
        __half2 p2 = __floats2half2_rn(h0, h1v);
        po[t] = *(unsigned*)&p2;
    }
    ((uint4*)(g_h1 + (size_t)node * 256))[lane] = outv;
}

// ---- L4 (PROFILED): fp16 mma GEMM  [t|u] = h1 @ Wc ----------------------------
// 256 threads, 2 CTAs/SM; block tile 64x256; warp tile 32x64 (2M x 4N warps).
// NN = 64 * 3125 exactly: no tail.
__global__ void __launch_bounds__(256, 2) k_gemm() {
    __shared__ __half As[BM][BK + 24];   // stride 112B (conflict-free ldmatrix)
    __shared__ __half Bs[BK][BN + 8];    // stride 528B

    int tid = threadIdx.x;
    int warp = tid >> 5, lane = tid & 31;
    int wm = warp & 1, wn = warp >> 1;   // 2(M) x 4(N) warps
    int bm = blockIdx.x * BM;

    float c[2][8][4];
    #pragma unroll
    for (int mi = 0; mi < 2; mi++)
        #pragma unroll
        for (int ni = 0; ni < 8; ni++)
            #pragma unroll
            for (int q = 0; q < 4; q++) c[mi][ni][q] = 0.0f;

    for (int k0 = 0; k0 < KH; k0 += BK) {
        // A tile: 64 x 32 fp16 (1 uint4 per thread, no tail guard: exact fit)
        {
            int row = tid >> 2, cq = tid & 3;
            *(uint4*)(&As[row][cq * 8]) =
                *(const uint4*)(g_h1 + (size_t)(bm + row) * 256 + k0 + cq * 8);
        }
        // B tile: 32 x 256 fp16 (4 uint4 per thread)
        #pragma unroll
        for (int r = 0; r < 4; r++) {
            int u = tid + 256 * r;
            int row = u >> 5, cq = u & 31;
            *(uint4*)(&Bs[row][cq * 8]) =
                *(const uint4*)(g_Wc + (size_t)(k0 + row) * 256 + cq * 8);
        }
        __syncthreads();

        #pragma unroll
        for (int kk = 0; kk < BK; kk += 16) {
            uint32_t a[2][4];
            #pragma unroll
            for (int mi = 0; mi < 2; mi++) {
                int r = wm * 32 + mi * 16 + (lane & 7) + 8 * ((lane >> 3) & 1);
                int cc = kk + 8 * (lane >> 4);
                uint32_t addr = (uint32_t)__cvta_generic_to_shared(&As[r][cc]);
                asm volatile("ldmatrix.sync.aligned.m8n8.x4.shared.b16 {%0,%1,%2,%3}, [%4];"
                             : "=r"(a[mi][0]), "=r"(a[mi][1]), "=r"(a[mi][2]), "=r"(a[mi][3])
                             : "r"(addr));
            }
            int rr = kk + (lane & 7) + 8 * ((lane >> 3) & 1);
            #pragma unroll
            for (int np = 0; np < 4; np++) {
                int ncol = wn * 64 + np * 16 + 8 * (lane >> 4);
                uint32_t b[4];
                uint32_t baddr = (uint32_t)__cvta_generic_to_shared(&Bs[rr][ncol]);
                asm volatile("ldmatrix.sync.aligned.m8n8.x4.trans.shared.b16 {%0,%1,%2,%3}, [%4];"
                             : "=r"(b[0]), "=r"(b[1]), "=r"(b[2]), "=r"(b[3])
                             : "r"(baddr));
                #pragma unroll
                for (int mi = 0; mi < 2; mi++) {
                    #pragma unroll
                    for (int h = 0; h < 2; h++) {
                        int ni = np * 2 + h;
                        asm volatile(
                            "mma.sync.aligned.m16n8k16.row.col.f32.f16.f16.f32 "
                            "{%0,%1,%2,%3},{%4,%5,%6,%7},{%8,%9},{%0,%1,%2,%3};"
                            : "+f"(c[mi][ni][0]), "+f"(c[mi][ni][1]),
                              "+f"(c[mi][ni][2]), "+f"(c[mi][ni][3])
                            : "r"(a[mi][0]), "r"(a[mi][1]), "r"(a[mi][2]), "r"(a[mi][3]),
                              "r"(b[2 * h]), "r"(b[2 * h + 1]));
                    }
                }
            }
        }
        __syncthreads();
    }

    // epilogue: fp16 store, cols <128 -> g_t, cols >=128 -> g_u (no tail)
    int gid = lane >> 2, qid = lane & 3;
    #pragma unroll
    for (int mi = 0; mi < 2; mi++) {
        int r0 = bm + wm * 32 + mi * 16 + gid;
        int r1 = r0 + 8;
        #pragma unroll
        for (int ni = 0; ni < 8; ni++) {
            int col = wn * 64 + ni * 8 + qid * 2;
            __half* base0;
            int cc;
            if (col < 128) { base0 = g_t; cc = col; }
            else           { base0 = g_u; cc = col - 128; }
            __half2 p0 = __floats2half2_rn(c[mi][ni][0], c[mi][ni][1]);
            *(unsigned*)(base0 + (size_t)r0 * 128 + cc) = *(unsigned*)&p0;
            __half2 p1 = __floats2half2_rn(c[mi][ni][2], c[mi][ni][3]);
            *(unsigned*)(base0 + (size_t)r1 * 128 + cc) = *(unsigned*)&p1;
        }
    }
}

// ---- L5: fill CSR (+ restore scan flags) --------------------------------------
__global__ void k_fill(const int* __restrict__ face) {
    int i = blockIdx.x * blockDim.x + threadIdx.x;
    if (i < NBLK) g_flag[i] = 0;            // restore invariant
    if (i >= NF) return;
    int v0 = face[i], v1 = face[NF + i], v2 = face[2 * NF + i];
    if (v0 != v1) g_colidx[atomicAdd(&g_cursor[v1], 1)] = v0;
    if (v1 != v2) g_colidx[atomicAdd(&g_cursor[v2], 1)] = v1;
    if (v0 != v2) g_colidx[atomicAdd(&g_cursor[v2], 1)] = v0;
}

// ---- L6: layer-2 aggregate + relu + mean-pool ---------------------------------
__global__ void k_layer2(const float* __restrict__ b2) {
    __shared__ float gsh[128];
    if (threadIdx.x < 128) gsh[threadIdx.x] = 0.0f;
    __syncthreads();

    int wid = threadIdx.x >> 5, lane = threadIdx.x & 31;
    int gwarp = blockIdx.x * (blockDim.x >> 5) + wid;
    int nwarps = gridDim.x * (blockDim.x >> 5);
    float4 bl = ((const float4*)b2)[lane];

    float a0 = 0.f, a1 = 0.f, a2 = 0.f, a3 = 0.f;
    for (int node = gwarp; node < NN; node += nwarps) {
        int beg = g_rowptr[node], end = g_rowptr[node + 1];
        float s0 = 0.f, s1 = 0.f, s2 = 0.f, s3 = 0.f;
        #pragma unroll 4
        for (int j = beg; j < end; j++) {
            int src = g_colidx[j];
            uint2 tv = ((const uint2*)(g_t + (size_t)src * 128))[lane];
            float2 t01 = __half22float2(*(__half2*)&tv.x);
            float2 t23 = __half22float2(*(__half2*)&tv.y);
            s0 += t01.x; s1 += t01.y;
            s2 += t23.x; s3 += t23.y;
        }
        float inv = 1.0f / fmaxf((float)(end - beg), 1.0f);
        uint2 uv = ((const uint2*)(g_u + (size_t)node * 128))[lane];
        float2 u01 = __half22float2(*(__half2*)&uv.x);
        float2 u23 = __half22float2(*(__half2*)&uv.y);
        a0 += fmaxf(s0 * inv + u01.x + bl.x, 0.0f);
        a1 += fmaxf(s1 * inv + u01.y + bl.y, 0.0f);
        a2 += fmaxf(s2 * inv + u23.x + bl.z, 0.0f);
        a3 += fmaxf(s3 * inv + u23.y + bl.w, 0.0f);
    }
    atomicAdd(&gsh[lane * 4 + 0], a0);
    atomicAdd(&gsh[lane * 4 + 1], a1);
    atomicAdd(&gsh[lane * 4 + 2], a2);
    atomicAdd(&gsh[lane * 4 + 3], a3);
    __syncthreads();
    if (threadIdx.x < 128) atomicAdd(&g_gsum[threadIdx.x], gsh[threadIdx.x]);
}

// ---- L7: decoder + softmax + argmax (+ restore gsum) ---------------------------
__global__ void k_final(const float* __restrict__ Wd, const float* __restrict__ bd,
                        float* __restrict__ out, int out_size) {
    if (threadIdx.x != 0 || blockIdx.x != 0) return;
    float g[128];
    for (int c = 0; c < 128; c++) {
        g[c] = g_gsum[c] * (1.0f / (float)NN);
        g_gsum[c] = 0.0f;   // restore invariant
    }
    float lg[10];
    for (int j = 0; j < 10; j++) lg[j] = bd[j];
    for (int c = 0; c < 128; c++) {
        float gv = g[c];
        for (int j = 0; j < 10; j++) lg[j] += gv * Wd[c * 10 + j];
    }
    float m = lg[0];
    for (int j = 1; j < 10; j++) m = fmaxf(m, lg[j]);
    float e[10], s = 0.0f;
    for (int j = 0; j < 10; j++) { e[j] = expf(lg[j] - m); s += e[j]; }
    float invs = 1.0f / s;
    int am = 0;
    float best = -1.0f;
    for (int j = 0; j < 10; j++) {
        float p = e[j] * invs;
        if (j < out_size) out[j] = p;
        if (p > best) { best = p; am = j; }
    }
    for (int i = 10; i < out_size; i++) out[i] = (float)am;
}

// ---------------- launch --------------------------------------------------------
extern "C" void kernel_launch(void* const* d_in, const int* in_sizes, int n_in,
                              void* d_out, int out_size) {
    const float* pos = (const float*)d_in[0];
    const int*   face = (const int*)d_in[1];
    const float* W1l = (const float*)d_in[2];
    const float* W1r = (const float*)d_in[3];
    const float* b1  = (const float*)d_in[4];
    const float* W2l = (const float*)d_in[5];
    const float* W2r = (const float*)d_in[6];
    const float* b2  = (const float*)d_in[7];
    const float* Wd  = (const float*)d_in[8];
    const float* bd  = (const float*)d_in[9];
    float* out = (float*)d_out;

    k_hist   <<<(NF + 255) / 256, 256>>>(face, pos, W2l, W2r);  // 1
    k_scan   <<<NBLK, 1024>>>();                                // 2
    k_layer1 <<<(NN + 7) / 8, 256>>>(pos, W1l, W1r, b1);        // 3
    k_gemm   <<<NN / BM, 256>>>();                              // 4  <- profiled
    k_fill   <<<(NF + 255) / 256, 256>>>(face);                 // 5
    k_layer2 <<<1184, 256>>>(b2);                               // 6
    k_final  <<<1, 32>>>(Wd, bd, out, out_size);                // 7
}